// round 12
// baseline (speedup 1.0000x reference)
#include <cuda_runtime.h>
#include <math.h>

// Fixed problem shapes
#define BB 16
#define HH 256
#define WW 256
#define SS 24
#define PS (HH * WW)             // per-channel plane stride
#define NPIX (BB * HH * WW)      // 1,048,576
#define NBLK 1024                // blocks: 4 rows per block
#define EPSF 1e-6f
#define WGRAD 0.05f

typedef unsigned long long ull;

__device__ float2 g_partials[NBLK];
__device__ unsigned int g_count = 0;

// ---------- packed f32x2 + MUFU helpers ----------
__device__ __forceinline__ ull pack2(float lo, float hi) {
    ull r; asm("mov.b64 %0, {%1, %2};" : "=l"(r) : "f"(lo), "f"(hi)); return r;
}
__device__ __forceinline__ void unpack2(ull v, float& lo, float& hi) {
    asm("mov.b64 {%0, %1}, %2;" : "=f"(lo), "=f"(hi) : "l"(v));
}
__device__ __forceinline__ ull fma2(ull a, ull b, ull c) {
    ull r; asm("fma.rn.f32x2 %0, %1, %2, %3;" : "=l"(r) : "l"(a), "l"(b), "l"(c)); return r;
}
__device__ __forceinline__ ull mul2(ull a, ull b) {
    ull r; asm("mul.rn.f32x2 %0, %1, %2;" : "=l"(r) : "l"(a), "l"(b)); return r;
}
__device__ __forceinline__ float sqrta(float x) {
    float r; asm("sqrt.approx.f32 %0, %1;" : "=f"(r) : "f"(x)); return r;
}
__device__ __forceinline__ float rsqrta(float x) {
    float r; asm("rsqrt.approx.f32 %0, %1;" : "=f"(r) : "f"(x)); return r;
}

// acos on [0,1]: deg-7 minimax, abs err ~2e-8 (validated rel_err 0.0)
__device__ __forceinline__ float acos_fast(float x) {
    float p = fmaf(x, -0.0012624911f, 0.0066700901f);
    p = fmaf(x, p, -0.0170881256f);
    p = fmaf(x, p,  0.0308918810f);
    p = fmaf(x, p, -0.0501743046f);
    p = fmaf(x, p,  0.0889789874f);
    p = fmaf(x, p, -0.2145988016f);
    p = fmaf(x, p,  1.5707963050f);
    return sqrta(1.0f - x) * p;
}

// one pixel's gradient-magnitude L1 contribution (raw, unnormalized quats)
__device__ __forceinline__ float grad_term(float pc, float pr, float pd,
                                           float tc, float tr, float td) {
    float gxp = pr - pc, gyp = pd - pc;
    float gxt = tr - tc, gyt = td - tc;
    float gp = sqrta(fmaf(gxp, gxp, fmaf(gyp, gyp, EPSF)));
    float gt = sqrta(fmaf(gxt, gxt, fmaf(gyt, gyt, EPSF)));
    return fabsf(gp - gt);
}

__global__ __launch_bounds__(256, 3) void fused_loss_kernel(
    const float* __restrict__ qp,
    const float* __restrict__ qt,
    const float* __restrict__ syms,
    float* __restrict__ out)
{
    // Sign-adjusted symmetry splats, packed 2-wide
    __shared__ ulonglong2 s2[SS][2];
    __shared__ float2 wsum[8];
    __shared__ bool amLast;

    const int tid = threadIdx.x;
    if (tid < SS) {
        float a =  syms[tid * 4 + 0];
        float bv = -syms[tid * 4 + 1];
        float c = -syms[tid * 4 + 2];
        float d = -syms[tid * 4 + 3];
        s2[tid][0] = make_ulonglong2(pack2(a, a), pack2(bv, bv));
        s2[tid][1] = make_ulonglong2(pack2(c, c), pack2(d, d));
    }
    __syncthreads();

    const ull NEG1 = pack2(-1.0f, -1.0f);

    // 4 rows per block, 64 threads per row, 4 pixels per thread (float4)
    const int row = (blockIdx.x << 2) + (tid >> 6);   // row = b*HH + h
    const int t   = tid & 63;
    const int b   = row >> 8;
    const int h   = row & (HH - 1);
    const int base = b * 4 * PS + h * WW + (t << 2);
    const int dh  = (h < HH - 1) ? WW : -WW;          // mirrored edge: |diff| identical
    const int lane = tid & 31;
    const int warp = tid >> 5;
    const bool hasr = (t < 63);
    const bool seam = (lane == 31);   // right neighbor not in this warp

    // ================= PHASE 1: front-batch ALL loads =================
    // 16 LDG.128 + 2 predicated seam LDGs issued back-to-back -> one DRAM
    // round trip per block instead of ~4 serialized ones. (84-reg budget)
    float4 P[4], T[4], PD[4], TD[4];
    float PRS[4], TRS[4];   // seam-lane right neighbors (predicated)
#pragma unroll
    for (int c = 0; c < 4; c++) {
        const float* pp = qp + base + c * PS;
        const float* tt = qt + base + c * PS;
        P[c]  = __ldg((const float4*)pp);
        T[c]  = __ldg((const float4*)tt);
        PD[c] = __ldg((const float4*)(pp + dh));
        TD[c] = __ldg((const float4*)(tt + dh));
        PRS[c] = (seam && hasr) ? __ldg(pp + 4) : 0.0f;
        TRS[c] = (seam && hasr) ? __ldg(tt + 4) : 0.0f;
    }

    // ================= PHASE 2: relquat (needs only P/T) =================
    // Runs while PD/TD/seam loads are still in flight.
    // r(p,t) is bilinear: r(p/|p|, t/|t|) = r(p,t) * (1/|p|)(1/|t|).
    ull RW[2], RX[2], RY[2], RZ[2];
    float s[4];
#pragma unroll
    for (int j = 0; j < 2; j++) {
        ull A0 = pack2(((const float*)&P[0])[2*j], ((const float*)&P[0])[2*j+1]);
        ull A1 = pack2(((const float*)&P[1])[2*j], ((const float*)&P[1])[2*j+1]);
        ull A2 = pack2(((const float*)&P[2])[2*j], ((const float*)&P[2])[2*j+1]);
        ull A3 = pack2(((const float*)&P[3])[2*j], ((const float*)&P[3])[2*j+1]);
        ull B0 = pack2(((const float*)&T[0])[2*j], ((const float*)&T[0])[2*j+1]);
        ull B1 = pack2(((const float*)&T[1])[2*j], ((const float*)&T[1])[2*j+1]);
        ull B2 = pack2(((const float*)&T[2])[2*j], ((const float*)&T[2])[2*j+1]);
        ull B3 = pack2(((const float*)&T[3])[2*j], ((const float*)&T[3])[2*j+1]);

        ull dp = fma2(A0, A0, fma2(A1, A1, fma2(A2, A2, mul2(A3, A3))));
        ull dt = fma2(B0, B0, fma2(B1, B1, fma2(B2, B2, mul2(B3, B3))));
        float dp0, dp1, dt0, dt1;
        unpack2(dp, dp0, dp1); unpack2(dt, dt0, dt1);
        s[2*j]   = rsqrta(dp0) * rsqrta(dt0);
        s[2*j+1] = rsqrta(dp1) * rsqrta(dt1);

        ull B0n = mul2(B0, NEG1);
        ull B1n = mul2(B1, NEG1);
        ull B2n = mul2(B2, NEG1);
        ull B3n = mul2(B3, NEG1);

        RW[j] = fma2(B0,  A0, fma2(B1,  A1, fma2(B2,  A2, mul2(B3,  A3))));
        RX[j] = fma2(B0n, A1, fma2(B1,  A0, fma2(B2n, A3, mul2(B3,  A2))));
        RY[j] = fma2(B0n, A2, fma2(B1,  A3, fma2(B2,  A0, mul2(B3n, A1))));
        RZ[j] = fma2(B0n, A3, fma2(B1n, A2, fma2(B2,  A1, mul2(B3,  A0))));
    }

    // ================= PHASE 3: gradient term (frees P/T/PD/TD) ==========
    float g0 = 0.0f, g1 = 0.0f;
#pragma unroll
    for (int c = 0; c < 4; c++) {
        float4 p  = P[c],  tq = T[c];
        float4 pd = PD[c], td = TD[c];

        float prn = __shfl_down_sync(0xFFFFFFFFu, p.x, 1);
        float trn = __shfl_down_sync(0xFFFFFFFFu, tq.x, 1);
        if (seam) {
            prn = hasr ? PRS[c] : p.z;   // mirrored image edge (|diff| equal)
            trn = hasr ? TRS[c] : tq.z;
        }

        g0 += grad_term(p.x, p.y, pd.x, tq.x, tq.y, td.x);
        g1 += grad_term(p.y, p.z, pd.y, tq.y, tq.z, td.y);
        g0 += grad_term(p.z, p.w, pd.z, tq.z, tq.w, td.z);
        g1 += grad_term(p.w, prn, pd.w, tq.w, trn, td.w);
    }
    float gsum = g0 + g1;

    // ================= PHASE 4: 24-symmetry max|dot| ====================
    float m0a = 0.0f, m1a = 0.0f, m2a = 0.0f, m3a = 0.0f;
    float m0b = 0.0f, m1b = 0.0f, m2b = 0.0f, m3b = 0.0f;
#pragma unroll
    for (int sy = 0; sy < SS; sy += 2) {
        {
            ulonglong2 vab = s2[sy][0];
            ulonglong2 vcd = s2[sy][1];
            ull d01 = fma2(RW[0], vab.x, fma2(RX[0], vab.y, fma2(RY[0], vcd.x, mul2(RZ[0], vcd.y))));
            ull d23 = fma2(RW[1], vab.x, fma2(RX[1], vab.y, fma2(RY[1], vcd.x, mul2(RZ[1], vcd.y))));
            float a, bb;
            unpack2(d01, a, bb); m0a = fmaxf(m0a, fabsf(a)); m1a = fmaxf(m1a, fabsf(bb));
            unpack2(d23, a, bb); m2a = fmaxf(m2a, fabsf(a)); m3a = fmaxf(m3a, fabsf(bb));
        }
        {
            ulonglong2 vab = s2[sy + 1][0];
            ulonglong2 vcd = s2[sy + 1][1];
            ull d01 = fma2(RW[0], vab.x, fma2(RX[0], vab.y, fma2(RY[0], vcd.x, mul2(RZ[0], vcd.y))));
            ull d23 = fma2(RW[1], vab.x, fma2(RX[1], vab.y, fma2(RY[1], vcd.x, mul2(RZ[1], vcd.y))));
            float a, bb;
            unpack2(d01, a, bb); m0b = fmaxf(m0b, fabsf(a)); m1b = fmaxf(m1b, fabsf(bb));
            unpack2(d23, a, bb); m2b = fmaxf(m2b, fabsf(a)); m3b = fmaxf(m3b, fabsf(bb));
        }
    }
    float m0 = fmaxf(m0a, m0b), m1 = fmaxf(m1a, m1b);
    float m2 = fmaxf(m2a, m2b), m3 = fmaxf(m3a, m3b);

    const float CL = 1.0f - EPSF;
    float rot = acos_fast(fminf(m0 * s[0], CL)) + acos_fast(fminf(m1 * s[1], CL))
              + acos_fast(fminf(m2 * s[2], CL)) + acos_fast(fminf(m3 * s[3], CL));
    rot *= 2.0f;

    // ---- block reduction ----
    float r = rot, g = gsum;
#pragma unroll
    for (int o = 16; o > 0; o >>= 1) {
        r += __shfl_xor_sync(0xFFFFFFFFu, r, o);
        g += __shfl_xor_sync(0xFFFFFFFFu, g, o);
    }
    if (lane == 0) wsum[warp] = make_float2(r, g);
    __syncthreads();
    if (warp == 0) {
        float2 v = (lane < 8) ? wsum[lane] : make_float2(0.0f, 0.0f);
        float rr = v.x, gg = v.y;
#pragma unroll
        for (int o = 4; o > 0; o >>= 1) {
            rr += __shfl_xor_sync(0xFFFFFFFFu, rr, o);
            gg += __shfl_xor_sync(0xFFFFFFFFu, gg, o);
        }
        if (lane == 0) {
            g_partials[blockIdx.x] = make_float2(rr, gg);
            __threadfence();
            unsigned int c = atomicAdd(&g_count, 1u);
            amLast = (c == NBLK - 1);
        }
    }
    __syncthreads();

    // ---- last block: grid-wide finish (deterministic fixed-order sum) ----
    if (amLast) {
        float r2 = 0.0f, g2 = 0.0f;
#pragma unroll
        for (int i = tid; i < NBLK; i += 256) {
            float2 v = __ldcg(&g_partials[i]);
            r2 += v.x; g2 += v.y;
        }
#pragma unroll
        for (int o = 16; o > 0; o >>= 1) {
            r2 += __shfl_xor_sync(0xFFFFFFFFu, r2, o);
            g2 += __shfl_xor_sync(0xFFFFFFFFu, g2, o);
        }
        if (lane == 0) wsum[warp] = make_float2(r2, g2);
        __syncthreads();
        if (tid == 0) {
            float rr = 0.0f, gg = 0.0f;
#pragma unroll
            for (int i = 0; i < 8; i++) { rr += wsum[i].x; gg += wsum[i].y; }
            out[0] = rr / (float)NPIX + WGRAD * (gg / (float)(4 * NPIX));
            g_count = 0;   // reset for next graph replay
        }
    }
}

extern "C" void kernel_launch(void* const* d_in, const int* in_sizes, int n_in,
                              void* d_out, int out_size)
{
    const float* qp   = (const float*)d_in[0];
    const float* qt   = (const float*)d_in[1];
    const float* syms = (const float*)d_in[2];
    float* out = (float*)d_out;

    fused_loss_kernel<<<NBLK, 256>>>(qp, qt, syms, out);
}